// round 17
// baseline (speedup 1.0000x reference)
#include <cuda_runtime.h>
#include <cuda_fp16.h>
#include <cstdint>

#define NQ      4
#define DIM     16
#define NHEADS  8
#define NLAYERS 2
#define EMBED   32
#define NBASIS  81
#define KS      6                // 6 k-steps of 16 -> K=96 (12 slots)
#define ROWF    36               // smem row stride in floats (padding vs 32)

// B operand in m16n8k16 fragment order, packed as uint4 covering an nt-PAIR
// (layout identical to R15/R16 — validated).
__device__ uint4 g_Bf4[NHEADS * KS * 2 * 32];

__device__ __forceinline__ uint32_t f2h2(float lo, float hi) {
    uint32_t r;
    asm("cvt.rn.f16x2.f32 %0, %1, %2;" : "=r"(r) : "f"(hi), "f"(lo));
    return r;
}

__device__ __forceinline__ void mma16816(float& d0, float& d1, float& d2, float& d3,
                                         uint32_t a0, uint32_t a1, uint32_t a2, uint32_t a3,
                                         uint32_t b0, uint32_t b1) {
    asm("mma.sync.aligned.m16n8k16.row.col.f32.f16.f16.f32 "
        "{%0,%1,%2,%3}, {%4,%5,%6,%7}, {%8,%9}, {%0,%1,%2,%3};"
        : "+f"(d0), "+f"(d1), "+f"(d2), "+f"(d3)
        : "r"(a0), "r"(a1), "r"(a2), "r"(a3), "r"(b0), "r"(b1));
}

// ---------------------------------------------------------------------------
// Precompute: per-head C pipeline + fragment-ordered B emission (validated).
// ---------------------------------------------------------------------------
__global__ void qmha_precompute(const float* __restrict__ params,
                                const float* __restrict__ W) {
    __shared__ float Ur[DIM][DIM];
    __shared__ float Ui[DIM][DIM];
    __shared__ float A[NQ][DIM * DIM];
    __shared__ float gc[NLAYERS * NQ * 3];
    __shared__ float gs[NLAYERS * NQ * 3];
    __shared__ float4 sC[NBASIS];

    const int h   = blockIdx.x;
    const int tid = threadIdx.x;

    if (tid < NLAYERS * NQ * 3) {
        const float th = params[h * NLAYERS * NQ * 3 + tid];
        float s, c;
        __sincosf(0.5f * th, &s, &c);
        gc[tid] = c;
        gs[tid] = s;
    }
    __syncthreads();

    if (tid < DIM) {
        float re[DIM], im[DIM];
        #pragma unroll
        for (int s = 0; s < DIM; s++) { re[s] = 0.f; im[s] = 0.f; }
        re[tid] = 1.f;

        for (int l = 0; l < NLAYERS; l++) {
            for (int w = 0; w < NQ; w++) {
                const int mask = 1 << (3 - w);
                const int gi = (l * NQ + w) * 3;
                const float cx = gc[gi + 0], sx = gs[gi + 0];
                const float cy = gc[gi + 1], sy = gs[gi + 1];
                const float cz = gc[gi + 2], sz = gs[gi + 2];
                #pragma unroll
                for (int s0 = 0; s0 < DIM; s0++) {
                    if (s0 & mask) continue;
                    const int s1 = s0 | mask;
                    float r0 = re[s0], i0 = im[s0], r1 = re[s1], i1 = im[s1];
                    float nr0 = cx * r0 + sx * i1;
                    float ni0 = cx * i0 - sx * r1;
                    float nr1 = sx * i0 + cx * r1;
                    float ni1 = -sx * r0 + cx * i1;
                    r0 = nr0; i0 = ni0; r1 = nr1; i1 = ni1;
                    nr0 = cy * r0 - sy * r1;
                    ni0 = cy * i0 - sy * i1;
                    nr1 = sy * r0 + cy * r1;
                    ni1 = sy * i0 + cy * i1;
                    r0 = nr0; i0 = ni0; r1 = nr1; i1 = ni1;
                    re[s0] = cz * r0 + sz * i0;
                    im[s0] = cz * i0 - sz * r0;
                    re[s1] = cz * r1 - sz * i1;
                    im[s1] = cz * i1 + sz * r1;
                }
            }
            #pragma unroll
            for (int e = 0; e < NQ; e++) {
                const int c = e, t = (e + 1) & 3;
                const int cm = 1 << (3 - c), tm = 1 << (3 - t);
                #pragma unroll
                for (int s = 0; s < DIM; s++) {
                    if ((s & cm) && !(s & tm)) {
                        const int s2 = s | tm;
                        float tr = re[s]; re[s] = re[s2]; re[s2] = tr;
                        float ti = im[s]; im[s] = im[s2]; im[s2] = ti;
                    }
                }
            }
        }
        #pragma unroll
        for (int s = 0; s < DIM; s++) { Ur[tid][s] = re[s]; Ui[tid][s] = im[s]; }
    }
    __syncthreads();

    {
        const int p = tid >> 4, q = tid & 15;
        float a0 = 0.f, a1 = 0.f, a2 = 0.f, a3 = 0.f;
        #pragma unroll
        for (int s = 0; s < DIM; s++) {
            float rr = Ur[p][s] * Ur[q][s] + Ui[p][s] * Ui[q][s];
            a0 += (s & 8) ? -rr : rr;
            a1 += (s & 4) ? -rr : rr;
            a2 += (s & 2) ? -rr : rr;
            a3 += (s & 1) ? -rr : rr;
        }
        A[0][tid] = a0; A[1][tid] = a1; A[2][tid] = a2; A[3][tid] = a3;
    }
    __syncthreads();

    if (tid < NBASIS) {
        int kw[4] = {tid / 27, (tid / 9) % 3, (tid / 3) % 3, tid % 3};
        float acc0 = 0.f, acc1 = 0.f, acc2 = 0.f, acc3 = 0.f;
        #pragma unroll
        for (int mm = 0; mm < 16; mm++) {
            int p = 0, q = 0;
            float wgt = 1.0f / 16.0f;
            #pragma unroll
            for (int w = 0; w < 4; w++) {
                const int opt = (mm >> w) & 1;
                const int kk = kw[w];
                int a, bb;
                if (kk == 0)      { a = opt; bb = opt; }
                else if (kk == 1) { a = opt; bb = opt; if (opt) wgt = -wgt; }
                else              { a = opt; bb = 1 - opt; }
                p |= a << (3 - w);
                q |= bb << (3 - w);
            }
            acc0 += wgt * A[0][p * 16 + q];
            acc1 += wgt * A[1][p * 16 + q];
            acc2 += wgt * A[2][p * 16 + q];
            acc3 += wgt * A[3][p * 16 + q];
        }
        sC[tid] = make_float4(acc0, acc1, acc2, acc3);
    }
    __syncthreads();

    for (int e = tid; e < KS * 2 * 32; e += 256) {
        const int ks = e >> 6;
        const int np = (e >> 5) & 1;
        const int lane = e & 31;
        const int m = lane & 3, g = lane >> 2;

        float vv[2][2][2];
        #pragma unroll
        for (int sub = 0; sub < 2; sub++) {
            const int n = (2 * np + sub) * 8 + g;
            const float* wr = W + n * 32 + h * 4;
            #pragma unroll
            for (int dh = 0; dh < 2; dh++) {
                #pragma unroll
                for (int eps = 0; eps < 2; eps++) {
                    const int slot = 2 * ks + dh;
                    float val = 0.f;
                    if (slot <= 8) {
                        const float4 c = sC[9 * slot + (2 * m + eps)];
                        val = c.x * wr[0] + c.y * wr[1] + c.z * wr[2] + c.w * wr[3];
                    } else {
                        const int p = slot - 9;
                        const int q = (m == 0) ? eps : ((m == 1 && eps == 0) ? 2 : -1);
                        if (q >= 0) {
                            const float4 c = sC[9 * (3 * p + q) + 8];
                            val = c.x * wr[0] + c.y * wr[1] + c.z * wr[2] + c.w * wr[3];
                        }
                    }
                    vv[sub][dh][eps] = val;
                }
            }
        }
        g_Bf4[(h * KS + ks) * 64 + np * 32 + lane] =
            make_uint4(f2h2(vv[0][0][0], vv[0][0][1]),
                       f2h2(vv[0][1][0], vv[0][1][1]),
                       f2h2(vv[1][0][0], vv[1][0][1]),
                       f2h2(vv[1][1][0], vv[1][1][1]));
    }
}

// Build the 12 slot registers for one token from staged (c,s) float4s.
__device__ __forceinline__ void build_slots(float4 c4, float4 s4, int m,
                                            uint32_t* S) {
    const float c2c3 = c4.z * c4.w, c2s3 = c4.z * s4.w;
    const float s2c3 = s4.z * c4.w, s2s3 = s4.z * s4.w;
    const float Px = (m & 2) ? ((m & 1) ? s4.z : c2c3) : ((m & 1) ? s4.w : 1.f);
    const float Py = (m & 2) ? ((m & 1) ? s2c3 : c2s3) : ((m & 1) ? c4.z : c4.w);
    const float Qx = (m & 2) ? 0.f : ((m & 1) ? s4.y * s2s3 : s2s3);
    const float Qy = (m == 0) ? c4.y * s2s3 : 0.f;

    const float A9[9] = {1.f, c4.y, s4.y, c4.x, c4.x * c4.y, c4.x * s4.y,
                         s4.x, s4.x * c4.y, s4.x * s4.y};
    #pragma unroll
    for (int i = 0; i < 9; i++) S[i] = f2h2(A9[i] * Px, A9[i] * Py);
    S[9]  = f2h2(Qx, Qy);
    S[10] = f2h2(c4.x * Qx, c4.x * Qy);
    S[11] = f2h2(s4.x * Qx, s4.x * Qy);
}

// ---------------------------------------------------------------------------
// Main: 128 tokens/block. Stage: block computes each sincos ONCE (32/thread,
// coalesced x loads) into padded smem (row stride 36 floats -> LDS.128 over
// 8 g-rows is bank-conflict-free). Mainloop: B double-buffered from global
// (R16-validated), A fragments built from staged (c,s) via broadcast LDS.
// ---------------------------------------------------------------------------
__global__ __launch_bounds__(128, 4) void qmha_mma(
    const float4* __restrict__ x,
    float*        __restrict__ out,
    const float*  __restrict__ bias)
{
    __shared__ float sc[128 * ROWF];   // cos rows
    __shared__ float ss[128 * ROWF];   // sin rows

    const int tid  = threadIdx.x;
    const int lane = tid & 31;
    const int warp = tid >> 5;
    const int m = lane & 3, g = lane >> 2;

    // --- staging: 1024 float4 = block's 128 tokens x 8 heads, coalesced ---
    {
        const float4* xb = x + blockIdx.x * 1024;
        #pragma unroll
        for (int k = 0; k < 8; k++) {
            const int e = tid + k * 128;      // f4 index: token = e>>3, head = e&7
            const float4 v = xb[e];
            float4 cv, sv;
            __sincosf(v.x, &sv.x, &cv.x);
            __sincosf(v.y, &sv.y, &cv.y);
            __sincosf(v.z, &sv.z, &cv.z);
            __sincosf(v.w, &sv.w, &cv.w);
            const int off = (e >> 3) * ROWF + (e & 7) * 4;
            *(float4*)(sc + off) = cv;
            *(float4*)(ss + off) = sv;
        }
    }
    __syncthreads();

    const int tbase = blockIdx.x * 128 + warp * 32;
    const int tok0 = tbase + g;
    const int tok1 = tbase + 8 + g;
    const int tok2 = tbase + 16 + g;
    const int tok3 = tbase + 24 + g;

    float acc[2][4][4];
    #pragma unroll
    for (int t = 0; t < 2; t++)
        #pragma unroll
        for (int nt = 0; nt < 4; nt++)
            #pragma unroll
            for (int r = 0; r < 4; r++) acc[t][nt][r] = 0.f;

    const uint4* BfL = g_Bf4 + lane;
    uint4 bA = __ldg(BfL);
    uint4 bB = __ldg(BfL + 32);

    #pragma unroll 1
    for (int h = 0; h < NHEADS; h++) {
        uint32_t S[4][12];
        #pragma unroll
        for (int cls = 0; cls < 4; cls++) {
            const int row = warp * 32 + cls * 8 + g;
            const int off = row * ROWF + h * 4;
            const float4 c4 = *(const float4*)(sc + off);
            const float4 s4 = *(const float4*)(ss + off);
            build_slots(c4, s4, m, S[cls]);
        }

        const uint4* Bf = BfL + h * KS * 64;
        #pragma unroll
        for (int ks = 0; ks < KS; ks++) {
            const uint4 cA = bA, cB = bB;
            const uint4* nxt = (ks + 1 < KS) ? (Bf + (ks + 1) * 64)
                                             : (BfL + ((h + 1) & 7) * KS * 64);
            bA = __ldg(nxt);
            bB = __ldg(nxt + 32);

            #pragma unroll
            for (int t = 0; t < 2; t++) {
                const uint32_t a0 = S[2 * t + 0][2 * ks];
                const uint32_t a1 = S[2 * t + 1][2 * ks];
                const uint32_t a2 = S[2 * t + 0][2 * ks + 1];
                const uint32_t a3 = S[2 * t + 1][2 * ks + 1];
                mma16816(acc[t][0][0], acc[t][0][1], acc[t][0][2], acc[t][0][3],
                         a0, a1, a2, a3, cA.x, cA.y);
                mma16816(acc[t][1][0], acc[t][1][1], acc[t][1][2], acc[t][1][3],
                         a0, a1, a2, a3, cA.z, cA.w);
                mma16816(acc[t][2][0], acc[t][2][1], acc[t][2][2], acc[t][2][3],
                         a0, a1, a2, a3, cB.x, cB.y);
                mma16816(acc[t][3][0], acc[t][3][1], acc[t][3][2], acc[t][3][3],
                         a0, a1, a2, a3, cB.z, cB.w);
            }
        }
    }

    #pragma unroll
    for (int t = 0; t < 2; t++) {
        const int tA = (t == 0) ? tok0 : tok2;
        const int tB = (t == 0) ? tok1 : tok3;
        #pragma unroll
        for (int nt = 0; nt < 4; nt++) {
            const int n0 = nt * 8 + 2 * m;
            const float2 bv = *(const float2*)(bias + n0);
            float2 oA; oA.x = acc[t][nt][0] + bv.x; oA.y = acc[t][nt][1] + bv.y;
            float2 oB; oB.x = acc[t][nt][2] + bv.x; oB.y = acc[t][nt][3] + bv.y;
            *(float2*)(out + tA * 32 + n0) = oA;
            *(float2*)(out + tB * 32 + n0) = oB;
        }
    }
}

extern "C" void kernel_launch(void* const* d_in, const int* in_sizes, int n_in,
                              void* d_out, int out_size) {
    const float* x      = (const float*)d_in[0];
    const float* params = (const float*)d_in[1];
    const float* W      = (const float*)d_in[2];
    const float* b      = (const float*)d_in[3];

    const int tokens = in_sizes[0] / EMBED;   // 131072

    qmha_precompute<<<NHEADS, 256>>>(params, W);

    const int blocks = tokens / 128;          // 1024
    qmha_mma<<<blocks, 128>>>((const float4*)x, (float*)d_out, b);
}